// round 10
// baseline (speedup 1.0000x reference)
#include <cuda_runtime.h>
#include <math.h>

#define NTOK 4096
#define DIM  1024
#define NEXP 8
#define CAP  1280
#define NSLOT (NTOK * 2)
#define ROWW (NEXP * CAP)            // 10240 floats per mask token-row

#define B_LOG   512                  // logits blocks: 1 token/warp, 8 warps
#define B_ZERO  2048                 // mask zero-fill blocks
#define B_BAT   (NEXP * CAP / 2)     // 5120 batch blocks (2 rows each)
#define SCAN_B  B_LOG                // 512
#define ZERO0   (B_LOG + 1)          // 513
#define BAT0    (ZERO0 + B_ZERO)     // 2561
#define NBLK    (BAT0 + B_BAT)       // 7681

// Scratch (no device allocs). All counters self-reset each launch.
__device__ int g_topidx[NSLOT];
__device__ int g_pos[NSLOT];
__device__ int g_inv[NEXP * CAP];
__device__ int g_done;               // logits blocks completed
__device__ int g_zero;               // zero blocks completed
__device__ int g_flag;               // scan complete
__device__ int g_bfin;               // batch blocks completed

__global__ __launch_bounds__(256)
void k_moe(const float* __restrict__ x, const float* __restrict__ Wg,
           float* __restrict__ gates, float* __restrict__ mask,
           float* __restrict__ batch) {
    __shared__ float4 sW[NEXP * DIM / 4];            // 32 KB (logits: W; scan: aliased)
    const int b = blockIdx.x;

    if (b >= BAT0) {
        // ---- exp_batches: wait for scan, 2 rows/block ----
        if (threadIdx.x == 0) {
            while (atomicAdd(&g_flag, 0) == 0) __nanosleep(64);
        }
        __syncthreads();
        __threadfence();
        int r0 = (b - BAT0) * 2;
#pragma unroll
        for (int j = 0; j < 2; j++) {
            int r = r0 + j;
            int t = g_inv[r];
            float4 v = make_float4(0.f, 0.f, 0.f, 0.f);
            if (t >= 0)
                v = ((const float4*)x)[(size_t)t * (DIM / 4) + threadIdx.x];
            __stcs((float4*)batch + (size_t)r * (DIM / 4) + threadIdx.x, v);
        }
        __syncthreads();
        if (threadIdx.x == 0) {
            int n = atomicAdd(&g_bfin, 1);
            if (n == B_BAT - 1) { g_flag = 0; g_bfin = 0; }   // replay reset
        }
        return;
    }

    if (b >= ZERO0) {
        // ---- mask zero-fill: independent, starts at t~0 ----
        int zb = b - ZERO0;                          // 0 .. 2047
        float4* dst = (float4*)mask + (size_t)zb * (256 * 20) + threadIdx.x;
        const float4 z = make_float4(0.f, 0.f, 0.f, 0.f);
#pragma unroll
        for (int j = 0; j < 20; j++)
            __stcs(dst + j * 256, z);
        __threadfence();
        __syncthreads();
        if (threadIdx.x == 0) atomicAdd(&g_zero, 1);
        return;
    }

    if (b < B_LOG) {
        // ---- logits: 1 token/warp, streamed x, W in shared ----
        const float4* W4 = (const float4*)Wg;
        for (int i = threadIdx.x; i < NEXP * DIM / 4; i += 256) sW[i] = W4[i];
        __syncthreads();

        int warp = threadIdx.x >> 5;
        int lane = threadIdx.x & 31;
        int t = b * 8 + warp;

        const float4* xr = (const float4*)x + (size_t)t * (DIM / 4);
        float acc[NEXP];
#pragma unroll
        for (int e = 0; e < NEXP; e++) acc[e] = 0.f;

#pragma unroll
        for (int i = 0; i < 8; i++) {
            int o = lane + 32 * i;
            float4 v = xr[o];
#pragma unroll
            for (int e = 0; e < NEXP; e++) {
                float4 w = sW[e * 256 + o];
                acc[e] += v.x * w.x + v.y * w.y + v.z * w.z + v.w * w.w;
            }
        }
#pragma unroll
        for (int off = 16; off; off >>= 1)
#pragma unroll
            for (int e = 0; e < NEXP; e++)
                acc[e] += __shfl_xor_sync(0xffffffffu, acc[e], off);

        if (lane == 0) {
            float v1 = -1e30f, v2 = -1e30f;
            int i1 = 0, i2 = 0;
#pragma unroll
            for (int e = 0; e < NEXP; e++) {
                float a = acc[e];
                if (a > v1)      { v2 = v1; i2 = i1; v1 = a; i1 = e; }
                else if (a > v2) { v2 = a;  i2 = e; }
            }
            float e2 = expf(v2 - v1);
            float inv = 1.f / (1.f + e2);
            gates[2 * t]     = inv;
            gates[2 * t + 1] = e2 * inv;
            g_topidx[2 * t]     = i1;
            g_topidx[2 * t + 1] = i2;
        }
        __syncthreads();
        __threadfence();
        if (threadIdx.x == 0) atomicAdd(&g_done, 1);
        return;
    }

    // ---- scan block (b == B_LOG) ----
    uint4* ssc = (uint4*)sW;                         // alias, scan doesn't use sW
    if (threadIdx.x == 0) {
        while (atomicAdd(&g_done, 0) < B_LOG) __nanosleep(64);
        g_done = 0;                                  // replay reset
    }
    __syncthreads();
    __threadfence();

    int tid = threadIdx.x;
    for (int i = tid; i < NEXP * CAP; i += 256) g_inv[i] = -1;

    int base = tid * 32;
    unsigned short h[NEXP];
#pragma unroll
    for (int e = 0; e < NEXP; e++) h[e] = 0;
#pragma unroll
    for (int j = 0; j < 32; j++) h[g_topidx[base + j]]++;

    uint4 v;
    v.x = (unsigned)h[0] | ((unsigned)h[1] << 16);
    v.y = (unsigned)h[2] | ((unsigned)h[3] << 16);
    v.z = (unsigned)h[4] | ((unsigned)h[5] << 16);
    v.w = (unsigned)h[6] | ((unsigned)h[7] << 16);
    ssc[tid] = v;
    __syncthreads();
    for (int off = 1; off < 256; off <<= 1) {
        uint4 a = make_uint4(0, 0, 0, 0);
        if (tid >= off) a = ssc[tid - off];
        __syncthreads();
        v.x += a.x; v.y += a.y; v.z += a.z; v.w += a.w;
        ssc[tid] = v;
        __syncthreads();
    }

    int cnt[NEXP];
    cnt[0] = (int)(v.x & 0xFFFF) - (int)h[0];
    cnt[1] = (int)(v.x >> 16)    - (int)h[1];
    cnt[2] = (int)(v.y & 0xFFFF) - (int)h[2];
    cnt[3] = (int)(v.y >> 16)    - (int)h[3];
    cnt[4] = (int)(v.z & 0xFFFF) - (int)h[4];
    cnt[5] = (int)(v.z >> 16)    - (int)h[5];
    cnt[6] = (int)(v.w & 0xFFFF) - (int)h[6];
    cnt[7] = (int)(v.w >> 16)    - (int)h[7];

#pragma unroll
    for (int j = 0; j < 32; j++) {
        int slot = base + j;
        int e = g_topidx[slot];                      // L1-hot reread, no reg array
        int p = cnt[e]++;
        if (p < CAP) {
            g_pos[slot] = p;
            g_inv[e * CAP + p] = slot >> 1;
        } else {
            g_pos[slot] = -1;
        }
    }
    __threadfence();
    __syncthreads();
    if (threadIdx.x == 0) atomicExch(&g_flag, 1);    // release batch blocks

    // wait for zero-fill completion, then scatter gates into mask
    if (threadIdx.x == 0) {
        while (atomicAdd(&g_zero, 0) < B_ZERO) __nanosleep(128);
        g_zero = 0;                                  // replay reset
    }
    __syncthreads();
    __threadfence();
#pragma unroll
    for (int j = 0; j < 32; j++) {
        int slot = base + j;
        int p = g_pos[slot];
        if (p >= 0) {
            int e = g_topidx[slot];
            int tok = slot >> 1;
            mask[(size_t)tok * ROWW + e * CAP + p] = gates[slot];
        }
    }
}

// ---------------------------------------------------------------------------
extern "C" void kernel_launch(void* const* d_in, const int* in_sizes, int n_in,
                              void* d_out, int out_size) {
    const float* x  = (const float*)d_in[0];   // [2,2048,1024] f32
    const float* Wg = (const float*)d_in[1];   // [8,1024] f32

    float* out   = (float*)d_out;
    float* gates = out;                                  // 8,192 floats
    float* mask  = out + (size_t)NSLOT;                  // 41,943,040 floats
    float* batch = mask + (size_t)NTOK * ROWW;           // 10,485,760 floats

    k_moe<<<NBLK, 256>>>(x, Wg, gates, mask, batch);
}

// round 11
// speedup vs baseline: 1.1170x; 1.1170x over previous
#include <cuda_runtime.h>
#include <math.h>

#define NTOK 4096
#define DIM  1024
#define NEXP 8
#define CAP  1280
#define NSLOT (NTOK * 2)
#define ROWW (NEXP * CAP)            // 10240 floats per mask token-row

// ---- node 1 layout: logits blocks then zero blocks, zero deps, zero atomics
#define B_LOG  512                   // 1 token/warp, 8 warps/block
#define B_ZERO 2048                  // 80 KB contiguous zero-fill each
#define NBLK1  (B_LOG + B_ZERO)      // 2560

// ---- node 2 layout: scan (bid 0) + batch + scatter
#define B_BAT  (NEXP * CAP / 2)      // 5120 blocks, 2 rows each
#define SCAT0  (1 + B_BAT)           // 5121
#define NBLK2  (SCAT0 + NSLOT / 256) // 5153

// Scratch (no device allocs)
__device__ int g_topidx[NSLOT];
__device__ int g_pos[NSLOT];
__device__ int g_inv[NEXP * CAP];
__device__ int g_flag;               // scan-complete; reset by node 1 bid 0

// ---------------------------------------------------------------------------
// Node 1: logits (global-W, L1-cached, no smem, no fences) + mask zero-fill.
// ---------------------------------------------------------------------------
__global__ __launch_bounds__(256) void k_pre(const float* __restrict__ x,
                                             const float* __restrict__ Wg,
                                             float* __restrict__ gates,
                                             float* __restrict__ mask) {
    const int b = blockIdx.x;

    if (b >= B_LOG) {
        // ----- mask zero-fill: stores only, no fence, no counter -----
        int zb = b - B_LOG;                          // 0 .. 2047
        float4* dst = (float4*)mask + (size_t)zb * (256 * 20) + threadIdx.x;
        const float4 z = make_float4(0.f, 0.f, 0.f, 0.f);
#pragma unroll
        for (int j = 0; j < 20; j++)
            __stcs(dst + j * 256, z);
        return;
    }

    if (b == 0 && threadIdx.x == 0) g_flag = 0;      // replay reset (stream-ordered)

    // ----- logits: 1 token/warp, x + W streamed from global (W hits L1) -----
    int warp = threadIdx.x >> 5;
    int lane = threadIdx.x & 31;
    int t = b * 8 + warp;

    const float4* xr = (const float4*)x + (size_t)t * (DIM / 4);
    const float4* W4 = (const float4*)Wg;

    float acc[NEXP];
#pragma unroll
    for (int e = 0; e < NEXP; e++) acc[e] = 0.f;

#pragma unroll
    for (int i = 0; i < 8; i++) {
        int o = lane + 32 * i;
        float4 v = xr[o];
#pragma unroll
        for (int e = 0; e < NEXP; e++) {
            float4 w = W4[e * 256 + o];              // same addr all warps -> L1
            acc[e] += v.x * w.x + v.y * w.y + v.z * w.z + v.w * w.w;
        }
    }
#pragma unroll
    for (int off = 16; off; off >>= 1)
#pragma unroll
        for (int e = 0; e < NEXP; e++)
            acc[e] += __shfl_xor_sync(0xffffffffu, acc[e], off);

    if (lane == 0) {
        float v1 = -1e30f, v2 = -1e30f;
        int i1 = 0, i2 = 0;
#pragma unroll
        for (int e = 0; e < NEXP; e++) {
            float a = acc[e];
            if (a > v1)      { v2 = v1; i2 = i1; v1 = a; i1 = e; }
            else if (a > v2) { v2 = a;  i2 = e; }
        }
        float e2 = expf(v2 - v1);
        float inv = 1.f / (1.f + e2);
        gates[2 * t]     = inv;
        gates[2 * t + 1] = e2 * inv;
        g_topidx[2 * t]     = i1;
        g_topidx[2 * t + 1] = i2;
    }
}

// ---------------------------------------------------------------------------
// Node 2: scan (bid 0) -> g_flag; batch rows + gate scatter spin on g_flag.
// All branches lightweight (4 KB smem, ~30 regs) -> high occupancy stores.
// ---------------------------------------------------------------------------
__global__ __launch_bounds__(256) void k_post(const float* __restrict__ x,
                                              const float* __restrict__ gates,
                                              float* __restrict__ mask,
                                              float* __restrict__ batch) {
    __shared__ uint4 ssc[256];                       // 4 KB (scan only)
    const int b = blockIdx.x;

    if (b == 0) {
        // ----- scan: positions + inverse map (g_topidx valid via node edge) -----
        int tid = threadIdx.x;
        for (int i = tid; i < NEXP * CAP; i += 256) g_inv[i] = -1;

        int base = tid * 32;
        unsigned short h[NEXP];
#pragma unroll
        for (int e = 0; e < NEXP; e++) h[e] = 0;
#pragma unroll
        for (int j = 0; j < 32; j++) h[g_topidx[base + j]]++;

        uint4 v;
        v.x = (unsigned)h[0] | ((unsigned)h[1] << 16);
        v.y = (unsigned)h[2] | ((unsigned)h[3] << 16);
        v.z = (unsigned)h[4] | ((unsigned)h[5] << 16);
        v.w = (unsigned)h[6] | ((unsigned)h[7] << 16);
        ssc[tid] = v;
        __syncthreads();
        for (int off = 1; off < 256; off <<= 1) {
            uint4 a = make_uint4(0, 0, 0, 0);
            if (tid >= off) a = ssc[tid - off];
            __syncthreads();
            v.x += a.x; v.y += a.y; v.z += a.z; v.w += a.w;
            ssc[tid] = v;
            __syncthreads();
        }

        int cnt[NEXP];
        cnt[0] = (int)(v.x & 0xFFFF) - (int)h[0];
        cnt[1] = (int)(v.x >> 16)    - (int)h[1];
        cnt[2] = (int)(v.y & 0xFFFF) - (int)h[2];
        cnt[3] = (int)(v.y >> 16)    - (int)h[3];
        cnt[4] = (int)(v.z & 0xFFFF) - (int)h[4];
        cnt[5] = (int)(v.z >> 16)    - (int)h[5];
        cnt[6] = (int)(v.w & 0xFFFF) - (int)h[6];
        cnt[7] = (int)(v.w >> 16)    - (int)h[7];

#pragma unroll
        for (int j = 0; j < 32; j++) {
            int slot = base + j;
            int e = g_topidx[slot];
            int p = cnt[e]++;
            if (p < CAP) {
                g_pos[slot] = p;
                g_inv[e * CAP + p] = slot >> 1;
            } else {
                g_pos[slot] = -1;
            }
        }
        __threadfence();
        __syncthreads();
        if (threadIdx.x == 0) atomicExch(&g_flag, 1);
        return;
    }

    // ----- everyone else waits for the scan (short spin, ~3 us) -----
    if (threadIdx.x == 0) {
        while (atomicAdd(&g_flag, 0) == 0) __nanosleep(64);
    }
    __syncthreads();
    __threadfence();

    if (b < SCAT0) {
        // ----- exp_batches: 2 rows per block -----
        int r0 = (b - 1) * 2;
#pragma unroll
        for (int j = 0; j < 2; j++) {
            int r = r0 + j;
            int t = g_inv[r];
            float4 v = make_float4(0.f, 0.f, 0.f, 0.f);
            if (t >= 0)
                v = ((const float4*)x)[(size_t)t * (DIM / 4) + threadIdx.x];
            __stcs((float4*)batch + (size_t)r * (DIM / 4) + threadIdx.x, v);
        }
    } else {
        // ----- scatter gates into the zeroed mask (zeroed in node 1) -----
        int slot = (b - SCAT0) * 256 + threadIdx.x;  // 0 .. NSLOT-1
        int p = g_pos[slot];
        if (p >= 0) {
            int e = g_topidx[slot];
            int tok = slot >> 1;
            mask[(size_t)tok * ROWW + e * CAP + p] = gates[slot];
        }
    }
}

// ---------------------------------------------------------------------------
extern "C" void kernel_launch(void* const* d_in, const int* in_sizes, int n_in,
                              void* d_out, int out_size) {
    const float* x  = (const float*)d_in[0];   // [2,2048,1024] f32
    const float* Wg = (const float*)d_in[1];   // [8,1024] f32

    float* out   = (float*)d_out;
    float* gates = out;                                  // 8,192 floats
    float* mask  = out + (size_t)NSLOT;                  // 41,943,040 floats
    float* batch = mask + (size_t)NTOK * ROWW;           // 10,485,760 floats

    k_pre<<<NBLK1, 256>>>(x, Wg, gates, mask);
    k_post<<<NBLK2, 256>>>(x, gates, mask, batch);
}

// round 12
// speedup vs baseline: 1.2122x; 1.0852x over previous
#include <cuda_runtime.h>
#include <math.h>

#define NTOK 4096
#define DIM  1024
#define NEXP 8
#define CAP  1280
#define NSLOT (NTOK * 2)
#define ROWW (NEXP * CAP)            // 10240 floats per mask token-row

// ---- node 1: logits (0..511) + scan (512) + zero-fill (513..2560)
#define B_LOG  512                   // 1 token/warp, 8 warps/block
#define B_ZERO 2048                  // 80 KB contiguous zero-fill each
#define ZERO0  (B_LOG + 1)           // 513
#define NBLK1  (ZERO0 + B_ZERO)      // 2561

// ---- node 2: batch rows + gate scatter (no spins; node edge is the barrier)
#define B_BAT  (NEXP * CAP / 2)      // 5120 blocks, 2 rows each
#define NBLK2  (B_BAT + NSLOT / 256) // 5152

// Scratch (no device allocs)
__device__ int g_topidx[NSLOT];
__device__ int g_pos[NSLOT];
__device__ int g_inv[NEXP * CAP];
__device__ int g_done;               // logits blocks completed (reset by scan)

// ---------------------------------------------------------------------------
// Node 1: logits (global-W via L1, no smem) + single-spinner scan + zero-fill.
// Zero blocks: stores only — no fences, no counters (proven 6.8 TB/s in R10).
// ---------------------------------------------------------------------------
__global__ __launch_bounds__(256) void k_pre(const float* __restrict__ x,
                                             const float* __restrict__ Wg,
                                             float* __restrict__ gates,
                                             float* __restrict__ mask) {
    __shared__ uint4 ssc[256];                       // 4 KB, scan branch only
    const int b = blockIdx.x;

    if (b >= ZERO0) {
        // ----- mask zero-fill: stores only -----
        int zb = b - ZERO0;                          // 0 .. 2047
        float4* dst = (float4*)mask + (size_t)zb * (256 * 20) + threadIdx.x;
        const float4 z = make_float4(0.f, 0.f, 0.f, 0.f);
#pragma unroll
        for (int j = 0; j < 20; j++)
            __stcs(dst + j * 256, z);
        return;
    }

    if (b < B_LOG) {
        // ----- logits: 1 token/warp, x + W streamed from global (W hits L1) -----
        int warp = threadIdx.x >> 5;
        int lane = threadIdx.x & 31;
        int t = b * 8 + warp;

        const float4* xr = (const float4*)x + (size_t)t * (DIM / 4);
        const float4* W4 = (const float4*)Wg;

        float acc[NEXP];
#pragma unroll
        for (int e = 0; e < NEXP; e++) acc[e] = 0.f;

#pragma unroll
        for (int i = 0; i < 8; i++) {
            int o = lane + 32 * i;
            float4 v = xr[o];
#pragma unroll
            for (int e = 0; e < NEXP; e++) {
                float4 w = W4[e * 256 + o];          // broadcast across warps -> L1
                acc[e] += v.x * w.x + v.y * w.y + v.z * w.z + v.w * w.w;
            }
        }
#pragma unroll
        for (int off = 16; off; off >>= 1)
#pragma unroll
            for (int e = 0; e < NEXP; e++)
                acc[e] += __shfl_xor_sync(0xffffffffu, acc[e], off);

        if (lane == 0) {
            float v1 = -1e30f, v2 = -1e30f;
            int i1 = 0, i2 = 0;
#pragma unroll
            for (int e = 0; e < NEXP; e++) {
                float a = acc[e];
                if (a > v1)      { v2 = v1; i2 = i1; v1 = a; i1 = e; }
                else if (a > v2) { v2 = a;  i2 = e; }
            }
            float e2 = expf(v2 - v1);
            float inv = 1.f / (1.f + e2);
            gates[2 * t]     = inv;
            gates[2 * t + 1] = e2 * inv;
            g_topidx[2 * t]     = i1;
            g_topidx[2 * t + 1] = i2;
        }
        __syncthreads();
        __threadfence();
        if (threadIdx.x == 0) atomicAdd(&g_done, 1);
        return;
    }

    // ----- scan block (b == B_LOG): the ONLY spinner -----
    if (threadIdx.x == 0) {
        while (atomicAdd(&g_done, 0) < B_LOG) __nanosleep(64);
        g_done = 0;                                  // replay reset
    }
    __syncthreads();
    __threadfence();

    int tid = threadIdx.x;
    for (int i = tid; i < NEXP * CAP; i += 256) g_inv[i] = -1;

    int base = tid * 32;
    unsigned short h[NEXP];
#pragma unroll
    for (int e = 0; e < NEXP; e++) h[e] = 0;
#pragma unroll
    for (int j = 0; j < 32; j++) h[g_topidx[base + j]]++;

    uint4 v;
    v.x = (unsigned)h[0] | ((unsigned)h[1] << 16);
    v.y = (unsigned)h[2] | ((unsigned)h[3] << 16);
    v.z = (unsigned)h[4] | ((unsigned)h[5] << 16);
    v.w = (unsigned)h[6] | ((unsigned)h[7] << 16);
    ssc[tid] = v;
    __syncthreads();
    for (int off = 1; off < 256; off <<= 1) {
        uint4 a = make_uint4(0, 0, 0, 0);
        if (tid >= off) a = ssc[tid - off];
        __syncthreads();
        v.x += a.x; v.y += a.y; v.z += a.z; v.w += a.w;
        ssc[tid] = v;
        __syncthreads();
    }

    int cnt[NEXP];
    cnt[0] = (int)(v.x & 0xFFFF) - (int)h[0];
    cnt[1] = (int)(v.x >> 16)    - (int)h[1];
    cnt[2] = (int)(v.y & 0xFFFF) - (int)h[2];
    cnt[3] = (int)(v.y >> 16)    - (int)h[3];
    cnt[4] = (int)(v.z & 0xFFFF) - (int)h[4];
    cnt[5] = (int)(v.z >> 16)    - (int)h[5];
    cnt[6] = (int)(v.w & 0xFFFF) - (int)h[6];
    cnt[7] = (int)(v.w >> 16)    - (int)h[7];

#pragma unroll
    for (int j = 0; j < 32; j++) {
        int slot = base + j;
        int e = g_topidx[slot];                      // L1-hot reread
        int p = cnt[e]++;
        if (p < CAP) {
            g_pos[slot] = p;
            g_inv[e * CAP + p] = slot >> 1;
        } else {
            g_pos[slot] = -1;
        }
    }
}

// ---------------------------------------------------------------------------
// Node 2: exp_batches (2 rows/block) + gate scatter. No spins, no flags —
// the kernel boundary orders it after the scan. (R8-proven shape, 11.9 us.)
// ---------------------------------------------------------------------------
__global__ __launch_bounds__(256) void k_out(const float* __restrict__ x,
                                             const float* __restrict__ gates,
                                             float* __restrict__ mask,
                                             float* __restrict__ batch) {
    int b = blockIdx.x;

    if (b < B_BAT) {
        // exp_batches: 2 rows per block (1024 floats = 256 x float4 each)
        int r0 = b * 2;
#pragma unroll
        for (int j = 0; j < 2; j++) {
            int r = r0 + j;
            int t = g_inv[r];
            float4 v = make_float4(0.f, 0.f, 0.f, 0.f);
            if (t >= 0)
                v = ((const float4*)x)[(size_t)t * (DIM / 4) + threadIdx.x];
            __stcs((float4*)batch + (size_t)r * (DIM / 4) + threadIdx.x, v);
        }
    } else {
        // scatter gates into the (node-1-zeroed) mask
        int slot = (b - B_BAT) * 256 + threadIdx.x;  // 0 .. NSLOT-1
        int p = g_pos[slot];
        if (p >= 0) {
            int e = g_topidx[slot];
            int tok = slot >> 1;
            mask[(size_t)tok * ROWW + e * CAP + p] = gates[slot];
        }
    }
}

// ---------------------------------------------------------------------------
extern "C" void kernel_launch(void* const* d_in, const int* in_sizes, int n_in,
                              void* d_out, int out_size) {
    const float* x  = (const float*)d_in[0];   // [2,2048,1024] f32
    const float* Wg = (const float*)d_in[1];   // [8,1024] f32

    float* out   = (float*)d_out;
    float* gates = out;                                  // 8,192 floats
    float* mask  = out + (size_t)NSLOT;                  // 41,943,040 floats
    float* batch = mask + (size_t)NTOK * ROWW;           // 10,485,760 floats

    k_pre<<<NBLK1, 256>>>(x, Wg, gates, mask);
    k_out<<<NBLK2, 256>>>(x, gates, mask, batch);
}